// round 16
// baseline (speedup 1.0000x reference)
#include <cuda_runtime.h>
#include <cuda_fp16.h>
#include <cstdint>

#define NB 8
#define SS 2048
#define DD 1024
#define AA 512
#define DVV 512

// GEMM tiling: 128x128 CTA tile, BK=64, 3-stage cp.async pipeline, swizzled smem
#define BM 128
#define BN 128
#define BKC 64
#define ROWB 128                      // bytes per smem row (64 fp16; XOR swizzle c^(row&7))
#define PLANE (128 * ROWB)            // 16384 B per operand plane
#define STAGE (2 * PLANE)             // 32768 B per stage [A|B]
#define NSTAGE 3
#define SMEM_PIPE (NSTAGE * STAGE)    // 98304 B

// ---------------------------------------------------------------------------
// Scratch (__device__ globals; allocation-free rule)
// ---------------------------------------------------------------------------
__device__ __half g_Qb[(size_t)NB * SS * DD];
__device__ __half g_Kb[(size_t)NB * SS * DD];
__device__ __half g_Vb[(size_t)NB * SS * DD];
__device__ __half g_Wq[(size_t)AA * DD];
__device__ __half g_Wk[(size_t)AA * DD];
__device__ __half g_Wv[(size_t)DVV * DD];
__device__ __half g_Qp[(size_t)NB * SS * AA];     // B of scores
__device__ __half g_Kp[(size_t)NB * SS * AA];     // A of scores
__device__ __half g_WVT[(size_t)NB * DVV * SS];   // [b][v][s], B of out
__device__ __half g_At[(size_t)NB * SS * SS];     // A of out (fp16 attn)

// ---------------------------------------------------------------------------
// Helpers
// ---------------------------------------------------------------------------
__device__ __forceinline__ uint32_t smem_u32(const void* p) {
    uint32_t a;
    asm("{ .reg .u64 t; cvta.to.shared.u64 t, %1; cvt.u32.u64 %0, t; }" : "=r"(a) : "l"(p));
    return a;
}
__device__ __forceinline__ void cp16(uint32_t dst, const void* src) {
    asm volatile("cp.async.cg.shared.global [%0], [%1], 16;" :: "r"(dst), "l"(src));
}
#define CP_COMMIT() asm volatile("cp.async.commit_group;" ::: "memory")
#define CP_WAIT1()  asm volatile("cp.async.wait_group 1;" ::: "memory")
#define CP_WAIT0()  asm volatile("cp.async.wait_group 0;" ::: "memory")

__device__ __forceinline__ void ldsm4(uint32_t (&r)[4], uint32_t addr) {
    asm volatile("ldmatrix.sync.aligned.m8n8.x4.shared.b16 {%0,%1,%2,%3}, [%4];"
        : "=r"(r[0]), "=r"(r[1]), "=r"(r[2]), "=r"(r[3]) : "r"(addr));
}
__device__ __forceinline__ void mma_f16(float* d, const uint32_t* a, uint32_t b0, uint32_t b1) {
    asm volatile("mma.sync.aligned.m16n8k16.row.col.f32.f16.f16.f32 "
        "{%0,%1,%2,%3}, {%4,%5,%6,%7}, {%8,%9}, {%0,%1,%2,%3};"
        : "+f"(d[0]), "+f"(d[1]), "+f"(d[2]), "+f"(d[3])
        : "r"(a[0]), "r"(a[1]), "r"(a[2]), "r"(a[3]), "r"(b0), "r"(b1));
}

// Per-lane ldmatrix offsets (plane-relative, swizzled). [subtile][ks], ks=0..3
struct FragOff { uint32_t a[4][4]; uint32_t b[2][4]; };
__device__ __forceinline__ void frag_offsets(int lane, int warp_m, int warp_n, FragOff& F) {
    int ha = lane >> 4;
#pragma unroll
    for (int wm = 0; wm < 4; wm++) {
        int row = warp_m * 64 + wm * 16 + (lane & 15);
        int x = row & 7;
#pragma unroll
        for (int ks = 0; ks < 4; ks++)
            F.a[wm][ks] = (uint32_t)(row * ROWB + (((ks * 2 + ha) ^ x) << 4));
    }
    int rb = (lane & 7) + ((lane >> 4) << 3);
    int hb = (lane & 8) ? 1 : 0;
#pragma unroll
    for (int p = 0; p < 2; p++) {
        int row = warp_n * 32 + p * 16 + rb;
        int x = row & 7;
#pragma unroll
        for (int ks = 0; ks < 4; ks++)
            F.b[p][ks] = (uint32_t)(row * ROWB + (((ks * 2 + hb) ^ x) << 4));
    }
}

// Issue cp.async for one BK=64 chunk (2 planes: A, B)
__device__ __forceinline__ void issue_cp(uint32_t sbase,
    const __half* __restrict__ A, int lda,
    const __half* __restrict__ B, int ldb,
    int k0, int tid)
{
    const int lrow = tid >> 1;
    const int half = tid & 1;
    const int x = lrow & 7;
    const int koff = k0 + half * 32;
    uint32_t rbase = sbase + (uint32_t)(lrow * ROWB);
    const __half* a0 = A + (size_t)lrow * lda + koff;
    const __half* b0 = B + (size_t)lrow * ldb + koff;
#pragma unroll
    for (int c = 0; c < 4; c++) {
        uint32_t off = (uint32_t)(((half * 4 + c) ^ x) << 4);
        cp16(rbase + off, a0 + c * 8);
        cp16(rbase + PLANE + off, b0 + c * 8);
    }
}

// One BK=64 chunk of fp16 1-pass MMA (4 k-steps)
__device__ __forceinline__ void mma_chunk64(uint32_t sb, const FragOff& F, float (*acc)[4][4]) {
#pragma unroll
    for (int ks = 0; ks < 4; ks++) {
        uint32_t af[4][4], bh[2][4];
#pragma unroll
        for (int wm = 0; wm < 4; wm++) ldsm4(af[wm], sb + F.a[wm][ks]);
#pragma unroll
        for (int p = 0; p < 2; p++) ldsm4(bh[p], sb + PLANE + F.b[p][ks]);
#pragma unroll
        for (int wm = 0; wm < 4; wm++)
#pragma unroll
            for (int wn = 0; wn < 4; wn++)
                mma_f16(acc[wm][wn], af[wm], bh[wn >> 1][(wn & 1) * 2], bh[wn >> 1][(wn & 1) * 2 + 1]);
    }
}

// 3-stage pipelined fp16 GEMM core, 2-chunk lookahead (acc += A * B^T over K)
__device__ __forceinline__ void gemm_core(uint32_t sb,
    const __half* A, int lda, const __half* B, int ldb,
    int K, int tid, const FragOff& F, float (*acc)[4][4])
{
    const int nch = K / BKC;
    issue_cp(sb, A, lda, B, ldb, 0, tid);
    CP_COMMIT();
    issue_cp(sb + STAGE, A, lda, B, ldb, BKC, tid);
    CP_COMMIT();
    uint32_t cur = 0, nxt2 = 2 * STAGE;
    for (int ch = 0; ch < nch; ch++) {
        if (ch < nch - 1) { CP_WAIT1(); } else { CP_WAIT0(); }
        __syncthreads();
        if (ch + 2 < nch) {
            issue_cp(sb + nxt2, A, lda, B, ldb, (ch + 2) * BKC, tid);
            CP_COMMIT();
        }
        mma_chunk64(sb + cur, F, acc);
        cur = (cur == (NSTAGE - 1) * STAGE) ? 0 : cur + STAGE;
        nxt2 = (nxt2 == (NSTAGE - 1) * STAGE) ? 0 : nxt2 + STAGE;
    }
    __syncthreads();
}

// ---------------------------------------------------------------------------
// Fused elementwise fp32 -> fp16 convert (6 tensors via blockIdx.z, per-z n4)
// ---------------------------------------------------------------------------
struct ConvArgs {
    const float* in[6];
    __half* hi[6];
    int n4[6];
};
__global__ void conv6_kernel(ConvArgs a)
{
    int z = blockIdx.z;
    int i = blockIdx.x * blockDim.x + threadIdx.x;
    if (i < a.n4[z]) {
        float4 v = reinterpret_cast<const float4*>(a.in[z])[i];
        __half2 h01 = __floats2half2_rn(v.x, v.y);
        __half2 h23 = __floats2half2_rn(v.z, v.w);
        reinterpret_cast<uint2*>(a.hi[z])[i] =
            make_uint2(*reinterpret_cast<uint32_t*>(&h01), *reinterpret_cast<uint32_t*>(&h23));
    }
}

// ---------------------------------------------------------------------------
// Fused projection (Q/K/V via blockIdx.z): C = A*W^T + bias -> fp16.
// z==2 (V): writes WVT[b][n][s] via smem transpose.
// ---------------------------------------------------------------------------
struct ProjArgs {
    const __half *Ain[3], *Win[3];
    const float* bias[3];
    __half *Cout[3];
};
__global__ __launch_bounds__(256, 2)
void proj_kernel(ProjArgs P)
{
    extern __shared__ char smem[];
    uint32_t sb = smem_u32(smem);
    const int tid = threadIdx.x, lane = tid & 31, wid = tid >> 5;
    const int warp_m = wid & 1, warp_n = wid >> 1;
    const int m0 = blockIdx.y * BM, n0 = blockIdx.x * BN;
    const int z = blockIdx.z;
    const __half* A = P.Ain[z];
    const __half* W = P.Win[z];
    const float* bias = P.bias[z];
    __half* C = P.Cout[z];

    float acc[4][4][4];
#pragma unroll
    for (int i = 0; i < 4; i++)
#pragma unroll
        for (int j = 0; j < 4; j++)
#pragma unroll
            for (int r = 0; r < 4; r++) acc[i][j][r] = 0.f;

    FragOff F;
    frag_offsets(lane, warp_m, warp_n, F);

    gemm_core(sb, A + (size_t)m0 * DD, DD, W + (size_t)n0 * DD, DD,
              DD, tid, F, acc);

    if (z != 2) {
#pragma unroll
        for (int wn = 0; wn < 4; wn++) {
            int n = n0 + warp_n * 32 + wn * 8 + (lane & 3) * 2;
            float b0 = bias[n], b1 = bias[n + 1];
#pragma unroll
            for (int wm = 0; wm < 4; wm++)
#pragma unroll
                for (int h = 0; h < 2; h++) {
                    int m = m0 + warp_m * 64 + wm * 16 + (lane >> 2) + h * 8;
                    __half2 hv = __floats2half2_rn(acc[wm][wn][h * 2] + b0,
                                                   acc[wm][wn][h * 2 + 1] + b1);
                    *reinterpret_cast<__half2*>(C + (size_t)m * AA + n) = hv;
                }
        }
    } else {
        char* T = smem;   // 272B-stride rows
#pragma unroll
        for (int wn = 0; wn < 4; wn++) {
            int ln = warp_n * 32 + wn * 8 + (lane & 3) * 2;
            float b0 = bias[n0 + ln], b1 = bias[n0 + ln + 1];
#pragma unroll
            for (int wm = 0; wm < 4; wm++)
#pragma unroll
                for (int h = 0; h < 2; h++) {
                    int lm = warp_m * 64 + wm * 16 + (lane >> 2) + h * 8;
                    *reinterpret_cast<__half*>(T + ln * 272 + lm * 2) =
                        __float2half_rn(acc[wm][wn][h * 2] + b0);
                    *reinterpret_cast<__half*>(T + (ln + 1) * 272 + lm * 2) =
                        __float2half_rn(acc[wm][wn][h * 2 + 1] + b1);
                }
        }
        __syncthreads();
        int v = tid >> 1, hs = (tid & 1) * 64;
        size_t b = (size_t)(m0 >> 11);
        int s0 = m0 & (SS - 1);
        __half* dh = C + (b * DVV + n0 + v) * SS + s0 + hs;
#pragma unroll
        for (int g = 0; g < 8; g++)
            *reinterpret_cast<uint4*>(dh + g * 8) =
                *reinterpret_cast<uint4*>(T + v * 272 + (hs + g * 8) * 2);
    }
}

// ---------------------------------------------------------------------------
// Scores (pre-transposed): attn[b][k][q] = scale*Kp[k]·Qp[q] - 1e9*mask[b][q][k]
// Mask read directly; writes fp32 logits into the attn slot of d_out.
// ---------------------------------------------------------------------------
__global__ __launch_bounds__(256, 2)
void scores_kernel(const __half* __restrict__ Kp, const __half* __restrict__ Qp,
                   const int* __restrict__ mask, float* __restrict__ attn)
{
    extern __shared__ char smem[];
    uint32_t sb = smem_u32(smem);
    const int tid = threadIdx.x, lane = tid & 31, wid = tid >> 5;
    const int warp_m = wid & 1, warp_n = wid >> 1;
    const int m0 = blockIdx.y * BM, n0 = blockIdx.x * BN, b = blockIdx.z;

    float acc[4][4][4];
#pragma unroll
    for (int i = 0; i < 4; i++)
#pragma unroll
        for (int j = 0; j < 4; j++)
#pragma unroll
            for (int r = 0; r < 4; r++) acc[i][j][r] = 0.f;

    FragOff F;
    frag_offsets(lane, warp_m, warp_n, F);

    const size_t base = (size_t)b * SS * AA;
    gemm_core(sb, Kp + base + (size_t)m0 * AA, AA,
              Qp + base + (size_t)n0 * AA, AA, AA, tid, F, acc);

    const float scale = 0.04419417382415922f;   // 1/sqrt(512)
    const int* mk = mask + (size_t)b * SS * SS;
    float* ab = attn + (size_t)b * SS * SS;
#pragma unroll
    for (int wm = 0; wm < 4; wm++)
#pragma unroll
        for (int h = 0; h < 2; h++) {
            int k = m0 + warp_m * 64 + wm * 16 + (lane >> 2) + h * 8;
#pragma unroll
            for (int wn = 0; wn < 4; wn++) {
                int q = n0 + warp_n * 32 + wn * 8 + (lane & 3) * 2;
                float mv0 = -1e9f * (float)mk[(size_t)q * SS + k];
                float mv1 = -1e9f * (float)mk[(size_t)(q + 1) * SS + k];
                *reinterpret_cast<float2*>(ab + (size_t)k * SS + q) =
                    make_float2(fmaf(acc[wm][wn][h * 2], scale, mv0),
                                fmaf(acc[wm][wn][h * 2 + 1], scale, mv1));
            }
        }
}

// ---------------------------------------------------------------------------
// Output: out[b][k][v] = sum_q attn[b][k][q] * WVT[b][v][q]
// ---------------------------------------------------------------------------
__global__ __launch_bounds__(256, 2)
void out_kernel(const __half* __restrict__ At,
                const __half* __restrict__ WVT, float* __restrict__ out)
{
    extern __shared__ char smem[];
    uint32_t sb = smem_u32(smem);
    const int tid = threadIdx.x, lane = tid & 31, wid = tid >> 5;
    const int warp_m = wid & 1, warp_n = wid >> 1;
    const int m0 = blockIdx.y * BM, n0 = blockIdx.x * BN, b = blockIdx.z;

    float acc[4][4][4];
#pragma unroll
    for (int i = 0; i < 4; i++)
#pragma unroll
        for (int j = 0; j < 4; j++)
#pragma unroll
            for (int r = 0; r < 4; r++) acc[i][j][r] = 0.f;

    FragOff F;
    frag_offsets(lane, warp_m, warp_n, F);

    const size_t abase = (size_t)b * SS * SS;
    const size_t bbase = (size_t)b * DVV * SS;
    gemm_core(sb, At + abase + (size_t)m0 * SS, SS,
              WVT + bbase + (size_t)n0 * SS, SS, SS, tid, F, acc);

    float* ob = out + (size_t)b * SS * DVV;
#pragma unroll
    for (int wm = 0; wm < 4; wm++)
#pragma unroll
        for (int h = 0; h < 2; h++) {
            int m = m0 + warp_m * 64 + wm * 16 + (lane >> 2) + h * 8;
#pragma unroll
            for (int wn = 0; wn < 4; wn++) {
                int n = n0 + warp_n * 32 + wn * 8 + (lane & 3) * 2;
                *reinterpret_cast<float2*>(ob + (size_t)m * DVV + n) =
                    make_float2(acc[wm][wn][h * 2], acc[wm][wn][h * 2 + 1]);
            }
        }
}

// ---------------------------------------------------------------------------
// In-place row softmax (fp32) + fp16 truncated write for the out GEMM.
// ---------------------------------------------------------------------------
__global__ void softmax_rows(float* __restrict__ p, __half* __restrict__ hi)
{
    __shared__ float red[33];
    size_t rb = (size_t)blockIdx.x * SS;
    float* x = p + rb;
    int tid = threadIdx.x;
    float v[8];
    float mx = -1e30f;
#pragma unroll
    for (int i = 0; i < 8; i++) { v[i] = x[tid + i * 256]; mx = fmaxf(mx, v[i]); }
#pragma unroll
    for (int o = 16; o > 0; o >>= 1) mx = fmaxf(mx, __shfl_xor_sync(0xffffffffu, mx, o));
    if ((tid & 31) == 0) red[tid >> 5] = mx;
    __syncthreads();
    if (tid < 32) {
        float m = (tid < 8) ? red[tid] : -1e30f;
#pragma unroll
        for (int o = 4; o > 0; o >>= 1) m = fmaxf(m, __shfl_xor_sync(0xffffffffu, m, o));
        if (tid == 0) red[32] = m;
    }
    __syncthreads();
    mx = red[32];
    float s = 0.f;
#pragma unroll
    for (int i = 0; i < 8; i++) { v[i] = __expf(v[i] - mx); s += v[i]; }
#pragma unroll
    for (int o = 16; o > 0; o >>= 1) s += __shfl_xor_sync(0xffffffffu, s, o);
    if ((tid & 31) == 0) red[tid >> 5] = s;
    __syncthreads();
    if (tid < 32) {
        float m = (tid < 8) ? red[tid] : 0.f;
#pragma unroll
        for (int o = 4; o > 0; o >>= 1) m += __shfl_xor_sync(0xffffffffu, m, o);
        if (tid == 0) red[32] = m;
    }
    __syncthreads();
    float inv = 1.0f / red[32];
#pragma unroll
    for (int i = 0; i < 8; i++) {
        int idx = tid + i * 256;
        float val = v[i] * inv;
        x[idx] = val;
        hi[rb + idx] = __float2half_rn(val);
    }
}

// ---------------------------------------------------------------------------
extern "C" void kernel_launch(void* const* d_in, const int* in_sizes, int n_in,
                              void* d_out, int out_size)
{
    const float* Q    = (const float*)d_in[0];
    const float* K    = (const float*)d_in[1];
    const float* V    = (const float*)d_in[2];
    const int*   mask = (const int*)  d_in[3];
    const float* Wq   = (const float*)d_in[4];
    const float* bq   = (const float*)d_in[5];
    const float* Wk   = (const float*)d_in[6];
    const float* bk   = (const float*)d_in[7];
    const float* Wv   = (const float*)d_in[8];
    const float* bv   = (const float*)d_in[9];

    float* out  = (float*)d_out;                   // selfOutput [B,S,Dv]
    float* attn = out + (size_t)NB * SS * DVV;     // attn       [B,S,S]

    static __half *pQb, *pKb, *pVb, *pWq, *pWk, *pWv;
    static __half *pQp, *pKp, *pWVT, *pAt;
    static bool inited = false;
    if (!inited) {
        cudaGetSymbolAddress((void**)&pQb, g_Qb);
        cudaGetSymbolAddress((void**)&pKb, g_Kb);
        cudaGetSymbolAddress((void**)&pVb, g_Vb);
        cudaGetSymbolAddress((void**)&pWq, g_Wq);
        cudaGetSymbolAddress((void**)&pWk, g_Wk);
        cudaGetSymbolAddress((void**)&pWv, g_Wv);
        cudaGetSymbolAddress((void**)&pQp, g_Qp);
        cudaGetSymbolAddress((void**)&pKp, g_Kp);
        cudaGetSymbolAddress((void**)&pWVT, g_WVT);
        cudaGetSymbolAddress((void**)&pAt, g_At);
        cudaFuncSetAttribute(proj_kernel,   cudaFuncAttributeMaxDynamicSharedMemorySize, SMEM_PIPE);
        cudaFuncSetAttribute(scores_kernel, cudaFuncAttributeMaxDynamicSharedMemorySize, SMEM_PIPE);
        cudaFuncSetAttribute(out_kernel,    cudaFuncAttributeMaxDynamicSharedMemorySize, SMEM_PIPE);
        inited = true;
    }

    // 1) Convert inputs + weights to fp16 in one launch
    {
        ConvArgs ca;
        int n4 = (NB * SS * DD) / 4;
        int w4 = (AA * DD) / 4;
        ca.in[0] = Q;  ca.hi[0] = pQb; ca.n4[0] = n4;
        ca.in[1] = K;  ca.hi[1] = pKb; ca.n4[1] = n4;
        ca.in[2] = V;  ca.hi[2] = pVb; ca.n4[2] = n4;
        ca.in[3] = Wq; ca.hi[3] = pWq; ca.n4[3] = w4;
        ca.in[4] = Wk; ca.hi[4] = pWk; ca.n4[4] = w4;
        ca.in[5] = Wv; ca.hi[5] = pWv; ca.n4[5] = w4;
        conv6_kernel<<<dim3((n4 + 255) / 256, 1, 6), 256>>>(ca);
    }

    // 2) Fused projections (all 1-pass fp16)
    {
        ProjArgs P;
        P.Ain[0] = pQb; P.Win[0] = pWq; P.bias[0] = bq; P.Cout[0] = pQp;
        P.Ain[1] = pKb; P.Win[1] = pWk; P.bias[1] = bk; P.Cout[1] = pKp;
        P.Ain[2] = pVb; P.Win[2] = pWv; P.bias[2] = bv; P.Cout[2] = pWVT;
        proj_kernel<<<dim3(4, 128, 3), 256, SMEM_PIPE>>>(P);
    }

    // 3) Masked, pre-transposed scores -> fp32 logits in attn slot of d_out
    scores_kernel<<<dim3(16, 16, NB), 256, SMEM_PIPE>>>(pKp, pQp, mask, attn);
    // 4) Row softmax in place + fp16 side-write
    softmax_rows<<<NB * SS, 256>>>(attn, pAt);
    // 5) selfOutput = attn @ WV  (K = 2048)
    out_kernel<<<dim3(4, 16, NB), 256, SMEM_PIPE>>>(pAt, pWVT, out);
}

// round 17
// speedup vs baseline: 1.4249x; 1.4249x over previous
#include <cuda_runtime.h>
#include <cuda_fp16.h>
#include <cstdint>

#define NB 8
#define SS 2048
#define DD 1024
#define AA 512
#define DVV 512

// GEMM tiling: 128x128 CTA tile, BK=64, 3-stage cp.async pipeline, swizzled smem
#define BM 128
#define BN 128
#define BKC 64
#define ROWB 128                      // bytes per smem row (64 fp16; XOR swizzle c^(row&7))
#define PLANE (128 * ROWB)            // 16384 B per operand plane
#define STAGE (2 * PLANE)             // 32768 B per stage [A|B]
#define NSTAGE 3
#define SMEM_PIPE (NSTAGE * STAGE)    // 98304 B

// ---------------------------------------------------------------------------
// Scratch (__device__ globals; allocation-free rule)
// ---------------------------------------------------------------------------
__device__ __half g_Qb[(size_t)NB * SS * DD];
__device__ __half g_Kb[(size_t)NB * SS * DD];
__device__ __half g_Vb[(size_t)NB * SS * DD];
__device__ __half g_Wq[(size_t)AA * DD];
__device__ __half g_Wk[(size_t)AA * DD];
__device__ __half g_Wv[(size_t)DVV * DD];
__device__ __half g_Qp[(size_t)NB * SS * AA];     // B of scores
__device__ __half g_Kp[(size_t)NB * SS * AA];     // A of scores
__device__ __half g_WVT[(size_t)NB * DVV * SS];   // [b][v][s], B of out
__device__ __half g_At[(size_t)NB * SS * SS];     // A of out (fp16 attn)

// ---------------------------------------------------------------------------
// Helpers
// ---------------------------------------------------------------------------
__device__ __forceinline__ uint32_t smem_u32(const void* p) {
    uint32_t a;
    asm("{ .reg .u64 t; cvta.to.shared.u64 t, %1; cvt.u32.u64 %0, t; }" : "=r"(a) : "l"(p));
    return a;
}
__device__ __forceinline__ void cp16(uint32_t dst, const void* src) {
    asm volatile("cp.async.cg.shared.global [%0], [%1], 16;" :: "r"(dst), "l"(src));
}
#define CP_COMMIT() asm volatile("cp.async.commit_group;" ::: "memory")
#define CP_WAIT1()  asm volatile("cp.async.wait_group 1;" ::: "memory")
#define CP_WAIT0()  asm volatile("cp.async.wait_group 0;" ::: "memory")

__device__ __forceinline__ void ldsm4(uint32_t (&r)[4], uint32_t addr) {
    asm volatile("ldmatrix.sync.aligned.m8n8.x4.shared.b16 {%0,%1,%2,%3}, [%4];"
        : "=r"(r[0]), "=r"(r[1]), "=r"(r[2]), "=r"(r[3]) : "r"(addr));
}
__device__ __forceinline__ void mma_f16(float* d, const uint32_t* a, uint32_t b0, uint32_t b1) {
    asm volatile("mma.sync.aligned.m16n8k16.row.col.f32.f16.f16.f32 "
        "{%0,%1,%2,%3}, {%4,%5,%6,%7}, {%8,%9}, {%0,%1,%2,%3};"
        : "+f"(d[0]), "+f"(d[1]), "+f"(d[2]), "+f"(d[3])
        : "r"(a[0]), "r"(a[1]), "r"(a[2]), "r"(a[3]), "r"(b0), "r"(b1));
}

// Per-lane ldmatrix offsets (plane-relative, swizzled). [subtile][ks], ks=0..3
struct FragOff { uint32_t a[4][4]; uint32_t b[2][4]; };
__device__ __forceinline__ void frag_offsets(int lane, int warp_m, int warp_n, FragOff& F) {
    int ha = lane >> 4;                      // A k-half (0/1) within 16-k step
#pragma unroll
    for (int wm = 0; wm < 4; wm++) {
        int row = warp_m * 64 + wm * 16 + (lane & 15);
        int x = row & 7;
#pragma unroll
        for (int ks = 0; ks < 4; ks++)
            F.a[wm][ks] = (uint32_t)(row * ROWB + (((ks * 2 + ha) ^ x) << 4));
    }
    int rb = (lane & 7) + ((lane >> 4) << 3);
    int hb = (lane & 8) ? 1 : 0;             // B k-half
#pragma unroll
    for (int p = 0; p < 2; p++) {
        int row = warp_n * 32 + p * 16 + rb;
        int x = row & 7;
#pragma unroll
        for (int ks = 0; ks < 4; ks++)
            F.b[p][ks] = (uint32_t)(row * ROWB + (((ks * 2 + hb) ^ x) << 4));
    }
}

// Issue cp.async for one BK=64 chunk (2 planes: A, B). Each thread: half a row
// (64B = 4 x 16B) per plane. 256 threads cover 128 rows x 2 halves.
__device__ __forceinline__ void issue_cp(uint32_t sbase,
    const __half* __restrict__ A, int lda,
    const __half* __restrict__ B, int ldb,
    int k0, int tid)
{
    const int lrow = tid >> 1;
    const int half = tid & 1;
    const int x = lrow & 7;
    const int koff = k0 + half * 32;
    uint32_t rbase = sbase + (uint32_t)(lrow * ROWB);
    const __half* a0 = A + (size_t)lrow * lda + koff;
    const __half* b0 = B + (size_t)lrow * ldb + koff;
#pragma unroll
    for (int c = 0; c < 4; c++) {
        uint32_t off = (uint32_t)(((half * 4 + c) ^ x) << 4);
        cp16(rbase + off, a0 + c * 8);
        cp16(rbase + PLANE + off, b0 + c * 8);
    }
}

// One BK=64 chunk of fp16 1-pass MMA (4 k-steps)
__device__ __forceinline__ void mma_chunk64(uint32_t sb, const FragOff& F, float (*acc)[4][4]) {
#pragma unroll
    for (int ks = 0; ks < 4; ks++) {
        uint32_t af[4][4], bh[2][4];
#pragma unroll
        for (int wm = 0; wm < 4; wm++) ldsm4(af[wm], sb + F.a[wm][ks]);
#pragma unroll
        for (int p = 0; p < 2; p++) ldsm4(bh[p], sb + PLANE + F.b[p][ks]);
#pragma unroll
        for (int wm = 0; wm < 4; wm++)
#pragma unroll
            for (int wn = 0; wn < 4; wn++)
                mma_f16(acc[wm][wn], af[wm], bh[wn >> 1][(wn & 1) * 2], bh[wn >> 1][(wn & 1) * 2 + 1]);
    }
}

// 3-stage pipelined fp16 GEMM core, 2-chunk lookahead (acc += A * B^T over K)
__device__ __forceinline__ void gemm_core(uint32_t sb,
    const __half* A, int lda, const __half* B, int ldb,
    int K, int tid, const FragOff& F, float (*acc)[4][4])
{
    const int nch = K / BKC;
    issue_cp(sb, A, lda, B, ldb, 0, tid);
    CP_COMMIT();
    issue_cp(sb + STAGE, A, lda, B, ldb, BKC, tid);
    CP_COMMIT();
    uint32_t cur = 0, nxt2 = 2 * STAGE;
    for (int ch = 0; ch < nch; ch++) {
        if (ch < nch - 1) { CP_WAIT1(); } else { CP_WAIT0(); }
        __syncthreads();
        if (ch + 2 < nch) {
            issue_cp(sb + nxt2, A, lda, B, ldb, (ch + 2) * BKC, tid);
            CP_COMMIT();
        }
        mma_chunk64(sb + cur, F, acc);
        cur = (cur == (NSTAGE - 1) * STAGE) ? 0 : cur + STAGE;
        nxt2 = (nxt2 == (NSTAGE - 1) * STAGE) ? 0 : nxt2 + STAGE;
    }
    __syncthreads();
}

// ---------------------------------------------------------------------------
// Fused elementwise fp32 -> fp16 convert (3 tensors via blockIdx.z)
// ---------------------------------------------------------------------------
struct ConvArgs {
    const float* in[3];
    __half* hi[3];
};
__global__ void conv3_kernel(ConvArgs a, int n4)
{
    int z = blockIdx.z;
    int i = blockIdx.x * blockDim.x + threadIdx.x;
    if (i < n4) {
        float4 v = reinterpret_cast<const float4*>(a.in[z])[i];
        __half2 h01 = __floats2half2_rn(v.x, v.y);
        __half2 h23 = __floats2half2_rn(v.z, v.w);
        reinterpret_cast<uint2*>(a.hi[z])[i] =
            make_uint2(*reinterpret_cast<uint32_t*>(&h01), *reinterpret_cast<uint32_t*>(&h23));
    }
}

// ---------------------------------------------------------------------------
// Fused projection (Q/K/V via blockIdx.z): C = A*W^T + bias -> fp16.
// z==2 (V): writes WVT[b][n][s] via smem transpose.
// ---------------------------------------------------------------------------
struct ProjArgs {
    const __half *Ain[3], *Win[3];
    const float* bias[3];
    __half *Cout[3];
};
__global__ __launch_bounds__(256, 2)
void proj_kernel(ProjArgs P)
{
    extern __shared__ char smem[];
    uint32_t sb = smem_u32(smem);
    const int tid = threadIdx.x, lane = tid & 31, wid = tid >> 5;
    const int warp_m = wid & 1, warp_n = wid >> 1;
    const int m0 = blockIdx.y * BM, n0 = blockIdx.x * BN;
    const int z = blockIdx.z;
    const __half* A = P.Ain[z];
    const __half* W = P.Win[z];
    const float* bias = P.bias[z];
    __half* C = P.Cout[z];

    float acc[4][4][4];
#pragma unroll
    for (int i = 0; i < 4; i++)
#pragma unroll
        for (int j = 0; j < 4; j++)
#pragma unroll
            for (int r = 0; r < 4; r++) acc[i][j][r] = 0.f;

    FragOff F;
    frag_offsets(lane, warp_m, warp_n, F);

    gemm_core(sb, A + (size_t)m0 * DD, DD, W + (size_t)n0 * DD, DD,
              DD, tid, F, acc);

    if (z != 2) {
#pragma unroll
        for (int wn = 0; wn < 4; wn++) {
            int n = n0 + warp_n * 32 + wn * 8 + (lane & 3) * 2;
            float b0 = bias[n], b1 = bias[n + 1];
#pragma unroll
            for (int wm = 0; wm < 4; wm++)
#pragma unroll
                for (int h = 0; h < 2; h++) {
                    int m = m0 + warp_m * 64 + wm * 16 + (lane >> 2) + h * 8;
                    __half2 hv = __floats2half2_rn(acc[wm][wn][h * 2] + b0,
                                                   acc[wm][wn][h * 2 + 1] + b1);
                    *reinterpret_cast<__half2*>(C + (size_t)m * AA + n) = hv;
                }
        }
    } else {
        char* T = smem;   // 272B-stride rows
#pragma unroll
        for (int wn = 0; wn < 4; wn++) {
            int ln = warp_n * 32 + wn * 8 + (lane & 3) * 2;
            float b0 = bias[n0 + ln], b1 = bias[n0 + ln + 1];
#pragma unroll
            for (int wm = 0; wm < 4; wm++)
#pragma unroll
                for (int h = 0; h < 2; h++) {
                    int lm = warp_m * 64 + wm * 16 + (lane >> 2) + h * 8;
                    *reinterpret_cast<__half*>(T + ln * 272 + lm * 2) =
                        __float2half_rn(acc[wm][wn][h * 2] + b0);
                    *reinterpret_cast<__half*>(T + (ln + 1) * 272 + lm * 2) =
                        __float2half_rn(acc[wm][wn][h * 2 + 1] + b1);
                }
        }
        __syncthreads();
        int v = tid >> 1, hs = (tid & 1) * 64;
        size_t b = (size_t)(m0 >> 11);
        int s0 = m0 & (SS - 1);
        __half* dh = C + (b * DVV + n0 + v) * SS + s0 + hs;
#pragma unroll
        for (int g = 0; g < 8; g++)
            *reinterpret_cast<uint4*>(dh + g * 8) =
                *reinterpret_cast<uint4*>(T + v * 272 + (hs + g * 8) * 2);
    }
}

// ---------------------------------------------------------------------------
// Scores (pre-transposed): attn[b][k][q] = scale*Kp[k]·Qp[q] - 1e9*mask[b][q][k]
// Mask read directly (sector-efficient transposed pattern); no maskT pre-pass.
// ---------------------------------------------------------------------------
__global__ __launch_bounds__(256, 2)
void scores_kernel(const __half* __restrict__ Kp, const __half* __restrict__ Qp,
                   const int* __restrict__ mask, float* __restrict__ attn)
{
    extern __shared__ char smem[];
    uint32_t sb = smem_u32(smem);
    const int tid = threadIdx.x, lane = tid & 31, wid = tid >> 5;
    const int warp_m = wid & 1, warp_n = wid >> 1;
    const int m0 = blockIdx.y * BM, n0 = blockIdx.x * BN, b = blockIdx.z;

    float acc[4][4][4];
#pragma unroll
    for (int i = 0; i < 4; i++)
#pragma unroll
        for (int j = 0; j < 4; j++)
#pragma unroll
            for (int r = 0; r < 4; r++) acc[i][j][r] = 0.f;

    FragOff F;
    frag_offsets(lane, warp_m, warp_n, F);

    const size_t base = (size_t)b * SS * AA;
    gemm_core(sb, Kp + base + (size_t)m0 * AA, AA,
              Qp + base + (size_t)n0 * AA, AA, AA, tid, F, acc);

    const float scale = 0.04419417382415922f;   // 1/sqrt(512)
    const int* mk = mask + (size_t)b * SS * SS;
    float* ab = attn + (size_t)b * SS * SS;
#pragma unroll
    for (int wm = 0; wm < 4; wm++)
#pragma unroll
        for (int h = 0; h < 2; h++) {
            int k = m0 + warp_m * 64 + wm * 16 + (lane >> 2) + h * 8;
#pragma unroll
            for (int wn = 0; wn < 4; wn++) {
                int q = n0 + warp_n * 32 + wn * 8 + (lane & 3) * 2;
                float mv0 = -1e9f * (float)mk[(size_t)q * SS + k];
                float mv1 = -1e9f * (float)mk[(size_t)(q + 1) * SS + k];
                *reinterpret_cast<float2*>(ab + (size_t)k * SS + q) =
                    make_float2(fmaf(acc[wm][wn][h * 2], scale, mv0),
                                fmaf(acc[wm][wn][h * 2 + 1], scale, mv1));
            }
        }
}

// ---------------------------------------------------------------------------
// Output: out[b][k][v] = sum_q attn[b][k][q] * WVT[b][v][q]
// ---------------------------------------------------------------------------
__global__ __launch_bounds__(256, 2)
void out_kernel(const __half* __restrict__ At,
                const __half* __restrict__ WVT, float* __restrict__ out)
{
    extern __shared__ char smem[];
    uint32_t sb = smem_u32(smem);
    const int tid = threadIdx.x, lane = tid & 31, wid = tid >> 5;
    const int warp_m = wid & 1, warp_n = wid >> 1;
    const int m0 = blockIdx.y * BM, n0 = blockIdx.x * BN, b = blockIdx.z;

    float acc[4][4][4];
#pragma unroll
    for (int i = 0; i < 4; i++)
#pragma unroll
        for (int j = 0; j < 4; j++)
#pragma unroll
            for (int r = 0; r < 4; r++) acc[i][j][r] = 0.f;

    FragOff F;
    frag_offsets(lane, warp_m, warp_n, F);

    const size_t abase = (size_t)b * SS * SS;
    const size_t bbase = (size_t)b * DVV * SS;
    gemm_core(sb, At + abase + (size_t)m0 * SS, SS,
              WVT + bbase + (size_t)n0 * SS, SS, SS, tid, F, acc);

    float* ob = out + (size_t)b * SS * DVV;
#pragma unroll
    for (int wm = 0; wm < 4; wm++)
#pragma unroll
        for (int h = 0; h < 2; h++) {
            int m = m0 + warp_m * 64 + wm * 16 + (lane >> 2) + h * 8;
#pragma unroll
            for (int wn = 0; wn < 4; wn++) {
                int n = n0 + warp_n * 32 + wn * 8 + (lane & 3) * 2;
                *reinterpret_cast<float2*>(ob + (size_t)m * DVV + n) =
                    make_float2(acc[wm][wn][h * 2], acc[wm][wn][h * 2 + 1]);
            }
        }
}

// ---------------------------------------------------------------------------
// In-place row softmax (fp32) + fp16 truncated write for the out GEMM.
// ---------------------------------------------------------------------------
__global__ void softmax_rows(float* __restrict__ p, __half* __restrict__ hi)
{
    __shared__ float red[33];
    size_t rb = (size_t)blockIdx.x * SS;
    float* x = p + rb;
    int tid = threadIdx.x;
    float v[8];
    float mx = -1e30f;
#pragma unroll
    for (int i = 0; i < 8; i++) { v[i] = x[tid + i * 256]; mx = fmaxf(mx, v[i]); }
#pragma unroll
    for (int o = 16; o > 0; o >>= 1) mx = fmaxf(mx, __shfl_xor_sync(0xffffffffu, mx, o));
    if ((tid & 31) == 0) red[tid >> 5] = mx;
    __syncthreads();
    if (tid < 32) {
        float m = (tid < 8) ? red[tid] : -1e30f;
#pragma unroll
        for (int o = 4; o > 0; o >>= 1) m = fmaxf(m, __shfl_xor_sync(0xffffffffu, m, o));
        if (tid == 0) red[32] = m;
    }
    __syncthreads();
    mx = red[32];
    float s = 0.f;
#pragma unroll
    for (int i = 0; i < 8; i++) { v[i] = __expf(v[i] - mx); s += v[i]; }
#pragma unroll
    for (int o = 16; o > 0; o >>= 1) s += __shfl_xor_sync(0xffffffffu, s, o);
    if ((tid & 31) == 0) red[tid >> 5] = s;
    __syncthreads();
    if (tid < 32) {
        float m = (tid < 8) ? red[tid] : 0.f;
#pragma unroll
        for (int o = 4; o > 0; o >>= 1) m += __shfl_xor_sync(0xffffffffu, m, o);
        if (tid == 0) red[32] = m;
    }
    __syncthreads();
    float inv = 1.0f / red[32];
#pragma unroll
    for (int i = 0; i < 8; i++) {
        int idx = tid + i * 256;
        float val = v[i] * inv;
        x[idx] = val;
        hi[rb + idx] = __float2half_rn(val);
    }
}

// ---------------------------------------------------------------------------
extern "C" void kernel_launch(void* const* d_in, const int* in_sizes, int n_in,
                              void* d_out, int out_size)
{
    const float* Q    = (const float*)d_in[0];
    const float* K    = (const float*)d_in[1];
    const float* V    = (const float*)d_in[2];
    const int*   mask = (const int*)  d_in[3];
    const float* Wq   = (const float*)d_in[4];
    const float* bq   = (const float*)d_in[5];
    const float* Wk   = (const float*)d_in[6];
    const float* bk   = (const float*)d_in[7];
    const float* Wv   = (const float*)d_in[8];
    const float* bv   = (const float*)d_in[9];

    float* out  = (float*)d_out;                   // selfOutput [B,S,Dv]
    float* attn = out + (size_t)NB * SS * DVV;     // attn       [B,S,S]

    static __half *pQb, *pKb, *pVb, *pWq, *pWk, *pWv;
    static __half *pQp, *pKp, *pWVT, *pAt;
    static bool inited = false;
    if (!inited) {
        cudaGetSymbolAddress((void**)&pQb, g_Qb);
        cudaGetSymbolAddress((void**)&pKb, g_Kb);
        cudaGetSymbolAddress((void**)&pVb, g_Vb);
        cudaGetSymbolAddress((void**)&pWq, g_Wq);
        cudaGetSymbolAddress((void**)&pWk, g_Wk);
        cudaGetSymbolAddress((void**)&pWv, g_Wv);
        cudaGetSymbolAddress((void**)&pQp, g_Qp);
        cudaGetSymbolAddress((void**)&pKp, g_Kp);
        cudaGetSymbolAddress((void**)&pWVT, g_WVT);
        cudaGetSymbolAddress((void**)&pAt, g_At);
        cudaFuncSetAttribute(proj_kernel,   cudaFuncAttributeMaxDynamicSharedMemorySize, SMEM_PIPE);
        cudaFuncSetAttribute(scores_kernel, cudaFuncAttributeMaxDynamicSharedMemorySize, SMEM_PIPE);
        cudaFuncSetAttribute(out_kernel,    cudaFuncAttributeMaxDynamicSharedMemorySize, SMEM_PIPE);
        inited = true;
    }

    // 1) Convert inputs + weights to fp16 (two launches, as in R14)
    {
        ConvArgs ca;
        ca.in[0] = Q; ca.in[1] = K; ca.in[2] = V;
        ca.hi[0] = pQb; ca.hi[1] = pKb; ca.hi[2] = pVb;
        int n4 = (NB * SS * DD) / 4;
        conv3_kernel<<<dim3((n4 + 255) / 256, 1, 3), 256>>>(ca, n4);

        ConvArgs cw;
        cw.in[0] = Wq; cw.in[1] = Wk; cw.in[2] = Wv;
        cw.hi[0] = pWq; cw.hi[1] = pWk; cw.hi[2] = pWv;
        int w4 = (AA * DD) / 4;
        conv3_kernel<<<dim3((w4 + 255) / 256, 1, 3), 256>>>(cw, w4);
    }

    // 2) Fused projections (all 1-pass fp16)
    {
        ProjArgs P;
        P.Ain[0] = pQb; P.Win[0] = pWq; P.bias[0] = bq; P.Cout[0] = pQp;
        P.Ain[1] = pKb; P.Win[1] = pWk; P.bias[1] = bk; P.Cout[1] = pKp;
        P.Ain[2] = pVb; P.Win[2] = pWv; P.bias[2] = bv; P.Cout[2] = pWVT;
        proj_kernel<<<dim3(4, 128, 3), 256, SMEM_PIPE>>>(P);
    }

    // 3) Masked, pre-transposed scores -> fp32 logits in attn slot of d_out
    scores_kernel<<<dim3(16, 16, NB), 256, SMEM_PIPE>>>(pKp, pQp, mask, attn);
    // 4) Row softmax in place + fp16 side-write
    softmax_rows<<<NB * SS, 256>>>(attn, pAt);
    // 5) selfOutput = attn @ WV  (K = 2048)
    out_kernel<<<dim3(4, 16, NB), 256, SMEM_PIPE>>>(pAt, pWVT, out);
}